// round 4
// baseline (speedup 1.0000x reference)
#include <cuda_runtime.h>

// Problem constants (fixed by the dataset)
constexpr int NN  = 50000;   // nodes
constexpr int EE  = 800000;  // edges
constexpr int PER = 200000;  // edges per emulsion order (EE/4)
constexpr int H   = 64;      // hidden dim
constexpr int RPB = 64;      // rows per fused block
constexpr int GRID = (NN + RPB - 1) / RPB;  // 782

typedef unsigned long long u64;

// ---------------- scratch (static device globals; no allocation) ----------
__device__ float g_x[NN * H];          // node features
__device__ float g_Ab[2][NN * H];      // dst-side pre-GEMM (double buffered)
__device__ float g_Bb[2][NN * H];      // src-side pre-GEMM (double buffered)
__device__ int   g_deg[5 * NN];        // degrees: 4 src-slices + 1 dst
__device__ int   g_off[5 * (NN + 1)];
__device__ int   g_cur[5 * (NN + 1)];
__device__ int2  g_edg[EE];            // src-CSR: (dst, ef bits)
__device__ int   g_nbr[EE];            // dst-CSR: src

// ---------------- packed f32x2 helpers -------------------------------------
__device__ __forceinline__ u64 pk(float lo, float hi) {
    u64 r; asm("mov.b64 %0, {%1, %2};" : "=l"(r) : "f"(lo), "f"(hi)); return r;
}
__device__ __forceinline__ float2 unpk(u64 v) {
    float2 f; asm("mov.b64 {%0, %1}, %2;" : "=f"(f.x), "=f"(f.y) : "l"(v)); return f;
}
__device__ __forceinline__ void ffma2(u64& d, u64 a, u64 b) {
    asm("fma.rn.f32x2 %0, %1, %2, %0;" : "+l"(d) : "l"(a), "l"(b));
}

// ---------------- CSR build ------------------------------------------------
__global__ void k_zero(int* p, int n) {
    int i = blockIdx.x * blockDim.x + threadIdx.x;
    if (i < n) p[i] = 0;
}

__global__ void k_hist(const int* __restrict__ ei) {
    int e = blockIdx.x * blockDim.x + threadIdx.x;
    if (e >= EE) return;
    int s = ei[e], d = ei[EE + e];
    int sl = e / PER;
    atomicAdd(&g_deg[sl * NN + s], 1);
    atomicAdd(&g_deg[4 * NN + d], 1);
}

// grid = 5 blocks (one per array), block = 1024
__global__ void k_scan() {
    int a = blockIdx.x;
    const int* deg = g_deg + a * NN;
    int* off = g_off + a * (NN + 1);
    int* cur = g_cur + a * (NN + 1);
    int t = threadIdx.x;
    const int CH = (NN + 1023) / 1024;  // 49
    int begin = t * CH;
    int end = begin + CH; if (end > NN) end = NN; if (begin > NN) begin = NN;
    int s = 0;
    for (int i = begin; i < end; i++) s += deg[i];
    __shared__ int sh[1024];
    sh[t] = s;
    __syncthreads();
    for (int d = 1; d < 1024; d <<= 1) {
        int v = 0;
        if (t >= d) v = sh[t - d];
        __syncthreads();
        if (t >= d) sh[t] += v;
        __syncthreads();
    }
    int pre = (t == 0) ? 0 : sh[t - 1];
    for (int i = begin; i < end; i++) {
        off[i] = pre; cur[i] = pre;
        pre += deg[i];
    }
    if (t == 1023) off[NN] = sh[1023];
}

__global__ void k_scatter(const int* __restrict__ ei, const float* __restrict__ ef) {
    int e = blockIdx.x * blockDim.x + threadIdx.x;
    if (e >= EE) return;
    int s = ei[e], d = ei[EE + e];
    int sl = e / PER;
    int p = atomicAdd(&g_cur[sl * (NN + 1) + s], 1);
    g_edg[sl * PER + p] = make_int2(d, __float_as_int(ef[e]));
    int q = atomicAdd(&g_cur[4 * (NN + 1) + d], 1);
    g_nbr[q] = s;
}

// ---------------- lin0 GEMM (K=10): g_x = relu(x0@W+b) ---------------------
__global__ void k_gemm1_k10(const float* __restrict__ xin, const float* __restrict__ W,
                            const float* __restrict__ bias, float* __restrict__ out,
                            int rowsPerBlock) {
    const int K = 10;
    int t = threadIdx.x;  // column
    float w[K];
#pragma unroll
    for (int k = 0; k < K; k++) w[k] = W[k * H + t];
    float bv = bias[t];
    __shared__ float xs[4][K];
    int row0 = blockIdx.x * rowsPerBlock;
    int row1 = row0 + rowsPerBlock; if (row1 > NN) row1 = NN;
    for (int r = row0; r < row1; r += 4) {
        for (int i = t; i < 4 * K; i += 64) xs[i / K][i % K] = xin[r * K + i];
        __syncthreads();
        float a0 = bv, a1 = bv, a2 = bv, a3 = bv;
#pragma unroll
        for (int k = 0; k < K; k++) {
            float wv = w[k];
            a0 = fmaf(xs[0][k], wv, a0);
            a1 = fmaf(xs[1][k], wv, a1);
            a2 = fmaf(xs[2][k], wv, a2);
            a3 = fmaf(xs[3][k], wv, a3);
        }
        out[(r + 0) * H + t] = fmaxf(a0, 0.f);
        out[(r + 1) * H + t] = fmaxf(a1, 0.f);
        out[(r + 2) * H + t] = fmaxf(a2, 0.f);
        out[(r + 3) * H + t] = fmaxf(a3, 0.f);
        __syncthreads();
    }
}

// ============================================================================
// Fused phase pieces. Block = 256 threads = 4 groups x 64 lanes.
// xs[64][64] holds this block's (updated) x rows.
// ============================================================================

// phase-1 EM: x'[n] = (x[n] + sum_e relu(A[dst_e] + B[n] + ef_e*w2)) / 2
__device__ __forceinline__ void phase1_em(
        float (*xs)[H], int grp, int lane, int row0, int nrows,
        const int* __restrict__ off, const int2* __restrict__ edg,
        const float* __restrict__ w2,
        const float* __restrict__ Aprev, const float* __restrict__ Bprev,
        bool write_x) {
    float w2v = w2[lane];
    for (int ni = grp; ni < RPB; ni += 4) {
        if (ni < nrows) {
            int n = row0 + ni;
            int e0 = off[n], e1 = off[n + 1];
            float yb = Bprev[n * H + lane];
            float a = 0.f;
            for (int e = e0; e < e1; e++) {
                int2 p = edg[e];
                a += fmaxf(Aprev[p.x * H + lane] + fmaf(__int_as_float(p.y), w2v, yb), 0.f);
            }
            float xv = (g_x[n * H + lane] + a) * 0.5f;
            if (write_x) g_x[n * H + lane] = xv;
            xs[ni][lane] = xv;
        } else {
            xs[ni][lane] = 0.f;
        }
    }
}

// phase-1 EC: x'[n] = max(0, max_e (A[n] + B[src_e]))  (does not read old x)
__device__ __forceinline__ void phase1_ec(
        float (*xs)[H], int grp, int lane, int row0, int nrows,
        const int* __restrict__ off, const int* __restrict__ nbr,
        const float* __restrict__ Aprev, const float* __restrict__ Bprev) {
    for (int ni = grp; ni < RPB; ni += 4) {
        if (ni < nrows) {
            int n = row0 + ni;
            int e0 = off[n], e1 = off[n + 1];
            float za = Aprev[n * H + lane];
            float a = 0.f;  // relu floor
            for (int e = e0; e < e1; e++) {
                int s = nbr[e];
                a = fmaxf(a, za + Bprev[s * H + lane]);
            }
            xs[ni][lane] = a;
        } else {
            xs[ni][lane] = 0.f;
        }
    }
}

// phase-1 LOAD: xs <- g_x rows (standalone dual-GEMM)
__device__ __forceinline__ void phase1_load(
        float (*xs)[H], int tid, int row0, int nrows) {
    const float4* src = (const float4*)(g_x + row0 * H);
    float4* dst = (float4*)xs;
    int nv = nrows * (H / 4);
    for (int i = tid; i < RPB * (H / 4); i += 256)
        dst[i] = (i < nv) ? src[i] : make_float4(0.f, 0.f, 0.f, 0.f);
}

// phase-2 dual GEMM: A' = xs@(W0-W1)(+bA), B' = xs@W1(+bB) for 16 rows per group
template <int BIAS_A, int BIAS_B>
__device__ __forceinline__ void phase2_dual(
        const float (*xs)[H], int grp, int c, int row0, int nrows,
        const float* __restrict__ Wg, const float* __restrict__ bias,
        float* __restrict__ Anext, float* __restrict__ Bnext) {
    u64 wA[32], wB[32];
#pragma unroll
    for (int k = 0; k < 32; k++) {
        float p0 = Wg[(H + 2 * k) * H + c], p1 = Wg[(H + 2 * k + 1) * H + c];
        wB[k] = pk(p0, p1);
        wA[k] = pk(Wg[(2 * k) * H + c] - p0, Wg[(2 * k + 1) * H + c] - p1);
    }
    float bA = BIAS_A ? bias[c] : 0.f;
    float bB = BIAS_B ? bias[c] : 0.f;
#pragma unroll 1
    for (int rb = grp * 16; rb < grp * 16 + 16; rb += 4) {
        if (rb >= nrows) break;
        const ulonglong2* x0 = (const ulonglong2*)xs[rb + 0];
        const ulonglong2* x1 = (const ulonglong2*)xs[rb + 1];
        const ulonglong2* x2 = (const ulonglong2*)xs[rb + 2];
        const ulonglong2* x3 = (const ulonglong2*)xs[rb + 3];
        u64 aA0 = 0, aA1 = 0, aA2 = 0, aA3 = 0;
        u64 aB0 = 0, aB1 = 0, aB2 = 0, aB3 = 0;
#pragma unroll
        for (int k2 = 0; k2 < 16; k2++) {
            ulonglong2 v0 = x0[k2], v1 = x1[k2], v2 = x2[k2], v3 = x3[k2];
            u64 wa0 = wA[2 * k2], wa1 = wA[2 * k2 + 1];
            u64 wb0 = wB[2 * k2], wb1 = wB[2 * k2 + 1];
            ffma2(aA0, v0.x, wa0); ffma2(aA0, v0.y, wa1);
            ffma2(aB0, v0.x, wb0); ffma2(aB0, v0.y, wb1);
            ffma2(aA1, v1.x, wa0); ffma2(aA1, v1.y, wa1);
            ffma2(aB1, v1.x, wb0); ffma2(aB1, v1.y, wb1);
            ffma2(aA2, v2.x, wa0); ffma2(aA2, v2.y, wa1);
            ffma2(aB2, v2.x, wb0); ffma2(aB2, v2.y, wb1);
            ffma2(aA3, v3.x, wa0); ffma2(aA3, v3.y, wa1);
            ffma2(aB3, v3.x, wb0); ffma2(aB3, v3.y, wb1);
        }
        int r = row0 + rb;
        float2 f;
        f = unpk(aA0); Anext[(r + 0) * H + c] = f.x + f.y + bA;
        f = unpk(aA1); Anext[(r + 1) * H + c] = f.x + f.y + bA;
        f = unpk(aA2); Anext[(r + 2) * H + c] = f.x + f.y + bA;
        f = unpk(aA3); Anext[(r + 3) * H + c] = f.x + f.y + bA;
        f = unpk(aB0); Bnext[(r + 0) * H + c] = f.x + f.y + bB;
        f = unpk(aB1); Bnext[(r + 1) * H + c] = f.x + f.y + bB;
        f = unpk(aB2); Bnext[(r + 2) * H + c] = f.x + f.y + bB;
        f = unpk(aB3); Bnext[(r + 3) * H + c] = f.x + f.y + bB;
    }
}

// phase-2 LIN: g_x = relu(xs@Wl + b)
__device__ __forceinline__ void phase2_lin(
        const float (*xs)[H], int grp, int c, int row0, int nrows,
        const float* __restrict__ Wl, const float* __restrict__ bias) {
    u64 wl[32];
#pragma unroll
    for (int k = 0; k < 32; k++)
        wl[k] = pk(Wl[(2 * k) * H + c], Wl[(2 * k + 1) * H + c]);
    float bv = bias[c];
#pragma unroll 1
    for (int rb = grp * 16; rb < grp * 16 + 16; rb += 4) {
        if (rb >= nrows) break;
        const ulonglong2* x0 = (const ulonglong2*)xs[rb + 0];
        const ulonglong2* x1 = (const ulonglong2*)xs[rb + 1];
        const ulonglong2* x2 = (const ulonglong2*)xs[rb + 2];
        const ulonglong2* x3 = (const ulonglong2*)xs[rb + 3];
        u64 a0 = 0, a1 = 0, a2 = 0, a3 = 0;
#pragma unroll
        for (int k2 = 0; k2 < 16; k2++) {
            ulonglong2 v0 = x0[k2], v1 = x1[k2], v2 = x2[k2], v3 = x3[k2];
            u64 w0 = wl[2 * k2], w1 = wl[2 * k2 + 1];
            ffma2(a0, v0.x, w0); ffma2(a0, v0.y, w1);
            ffma2(a1, v1.x, w0); ffma2(a1, v1.y, w1);
            ffma2(a2, v2.x, w0); ffma2(a2, v2.y, w1);
            ffma2(a3, v3.x, w0); ffma2(a3, v3.y, w1);
        }
        int r = row0 + rb;
        float2 f;
        f = unpk(a0); g_x[(r + 0) * H + c] = fmaxf(f.x + f.y + bv, 0.f);
        f = unpk(a1); g_x[(r + 1) * H + c] = fmaxf(f.x + f.y + bv, 0.f);
        f = unpk(a2); g_x[(r + 2) * H + c] = fmaxf(f.x + f.y + bv, 0.f);
        f = unpk(a3); g_x[(r + 3) * H + c] = fmaxf(f.x + f.y + bv, 0.f);
    }
}

// ---------------- fused kernels --------------------------------------------
template <int BIAS_A, int BIAS_B>
__global__ void __launch_bounds__(256) k_g2_load(
        const float* __restrict__ Wg, const float* __restrict__ bias,
        float* __restrict__ Anext, float* __restrict__ Bnext) {
    __shared__ __align__(16) float xs[RPB][H];
    int tid = threadIdx.x, grp = tid >> 6, lane = tid & 63;
    int row0 = blockIdx.x * RPB;
    int nrows = min(RPB, NN - row0);
    phase1_load(xs, tid, row0, nrows);
    __syncthreads();
    phase2_dual<BIAS_A, BIAS_B>(xs, grp, lane, row0, nrows, Wg, bias, Anext, Bnext);
}

template <int BIAS_A, int BIAS_B, int WRITE_X>
__global__ void __launch_bounds__(256) k_em_g2(
        const int* __restrict__ off, const int2* __restrict__ edg,
        const float* __restrict__ w2,
        const float* __restrict__ Aprev, const float* __restrict__ Bprev,
        const float* __restrict__ Wg, const float* __restrict__ bias,
        float* __restrict__ Anext, float* __restrict__ Bnext) {
    __shared__ __align__(16) float xs[RPB][H];
    int tid = threadIdx.x, grp = tid >> 6, lane = tid & 63;
    int row0 = blockIdx.x * RPB;
    int nrows = min(RPB, NN - row0);
    phase1_em(xs, grp, lane, row0, nrows, off, edg, w2, Aprev, Bprev, WRITE_X != 0);
    __syncthreads();
    phase2_dual<BIAS_A, BIAS_B>(xs, grp, lane, row0, nrows, Wg, bias, Anext, Bnext);
}

__global__ void __launch_bounds__(256) k_em_lin(
        const int* __restrict__ off, const int2* __restrict__ edg,
        const float* __restrict__ w2,
        const float* __restrict__ Aprev, const float* __restrict__ Bprev,
        const float* __restrict__ Wl, const float* __restrict__ bias) {
    __shared__ __align__(16) float xs[RPB][H];
    int tid = threadIdx.x, grp = tid >> 6, lane = tid & 63;
    int row0 = blockIdx.x * RPB;
    int nrows = min(RPB, NN - row0);
    phase1_em(xs, grp, lane, row0, nrows, off, edg, w2, Aprev, Bprev, false);
    __syncthreads();
    phase2_lin(xs, grp, lane, row0, nrows, Wl, bias);
}

template <int BIAS_A, int BIAS_B>
__global__ void __launch_bounds__(256) k_ec_g2(
        const int* __restrict__ off, const int* __restrict__ nbr,
        const float* __restrict__ Aprev, const float* __restrict__ Bprev,
        const float* __restrict__ Wg, const float* __restrict__ bias,
        float* __restrict__ Anext, float* __restrict__ Bnext) {
    __shared__ __align__(16) float xs[RPB][H];
    int tid = threadIdx.x, grp = tid >> 6, lane = tid & 63;
    int row0 = blockIdx.x * RPB;
    int nrows = min(RPB, NN - row0);
    phase1_ec(xs, grp, lane, row0, nrows, off, nbr, Aprev, Bprev);
    __syncthreads();
    phase2_dual<BIAS_A, BIAS_B>(xs, grp, lane, row0, nrows, Wg, bias, Anext, Bnext);
}

__global__ void __launch_bounds__(256) k_ec_out(
        const int* __restrict__ off, const int* __restrict__ nbr,
        const float* __restrict__ Aprev, const float* __restrict__ Bprev,
        const float* __restrict__ ow, const float* __restrict__ ob,
        float* __restrict__ out) {
    __shared__ __align__(16) float xs[RPB][H];
    __shared__ float ws[64 * 10];
    __shared__ float bs[10];
    int tid = threadIdx.x, grp = tid >> 6, lane = tid & 63;
    int row0 = blockIdx.x * RPB;
    int nrows = min(RPB, NN - row0);
    for (int i = tid; i < 640; i += 256) ws[i] = ow[i];
    if (tid < 10) bs[tid] = ob[tid];
    phase1_ec(xs, grp, lane, row0, nrows, off, nbr, Aprev, Bprev);
    __syncthreads();
    for (int idx = tid; idx < nrows * 10; idx += 256) {
        int ni = idx / 10, c = idx % 10;
        float acc = bs[c];
#pragma unroll
        for (int k = 0; k < 64; k++) acc = fmaf(xs[ni][k], ws[k * 10 + c], acc);
        out[(row0 + ni) * 10 + c] = acc;
    }
}

// ---------------- orchestration --------------------------------------------
extern "C" void kernel_launch(void* const* d_in, const int* in_sizes, int n_in,
                              void* d_out, int out_size) {
    const float* x0  = (const float*)d_in[0];
    const int*   ei  = (const int*)d_in[1];
    const float* ef  = (const float*)d_in[2];
    const float* lw[3] = {(const float*)d_in[3], (const float*)d_in[5], (const float*)d_in[7]};
    const float* lb[3] = {(const float*)d_in[4], (const float*)d_in[6], (const float*)d_in[8]};
    const float* emw = (const float*)d_in[9];   // [3,129,64]
    const float* emb = (const float*)d_in[10];  // [3,64]
    const float* ecw = (const float*)d_in[11];  // [3,128,64]
    const float* ecb = (const float*)d_in[12];  // [3,64]
    const float* ow  = (const float*)d_in[13];
    const float* ob  = (const float*)d_in[14];

    float *gx, *gA0, *gB0;
    int *gdeg, *goff, *gnbr;
    int2* gedg;
    cudaGetSymbolAddress((void**)&gx,   g_x);
    cudaGetSymbolAddress((void**)&gA0,  g_Ab);
    cudaGetSymbolAddress((void**)&gB0,  g_Bb);
    cudaGetSymbolAddress((void**)&gdeg, g_deg);
    cudaGetSymbolAddress((void**)&goff, g_off);
    cudaGetSymbolAddress((void**)&gnbr, g_nbr);
    cudaGetSymbolAddress((void**)&gedg, g_edg);
    float* A[2] = {gA0, gA0 + NN * H};
    float* B[2] = {gB0, gB0 + NN * H};

    // CSR build (per launch, deterministic workload)
    k_zero<<<(5 * NN + 255) / 256, 256>>>(gdeg, 5 * NN);
    k_hist<<<(EE + 255) / 256, 256>>>(ei);
    k_scan<<<5, 1024>>>();
    k_scatter<<<(EE + 255) / 256, 256>>>(ei, ef);

    const int RPB0 = 52;
    const int G0 = (NN + RPB0 - 1) / RPB0;
    const int* dstoff = goff + 4 * (NN + 1);

    // lin0
    k_gemm1_k10<<<G0, 64>>>(x0, lw[0], lb[0], gx, RPB0);

    int cur = 0;
    for (int L = 0; L < 3; L++) {
        const float* W  = emw + L * 129 * H;
        const float* w2 = W + 128 * H;
        const float* b  = emb + L * H;
        // standalone dual GEMM from g_x into buf0
        k_g2_load<0, 1><<<GRID, 256>>>(W, b, A[0], B[0]);
        cur = 0;
        // orders 0..2: em + next dual GEMM (same layer weights)
        for (int o = 0; o < 3; o++) {
            k_em_g2<0, 1, 1><<<GRID, 256>>>(goff + o * (NN + 1), gedg + o * PER, w2,
                                            A[cur], B[cur], W, b, A[1 - cur], B[1 - cur]);
            cur ^= 1;
        }
        // order 3: em + (lin of next layer | first EdgeConv dual GEMM)
        if (L < 2) {
            k_em_lin<<<GRID, 256>>>(goff + 3 * (NN + 1), gedg + 3 * PER, w2,
                                    A[cur], B[cur], lw[L + 1], lb[L + 1]);
        } else {
            k_em_g2<1, 0, 0><<<GRID, 256>>>(goff + 3 * (NN + 1), gedg + 3 * PER, w2,
                                            A[cur], B[cur], ecw, ecb, A[1 - cur], B[1 - cur]);
            cur ^= 1;
        }
    }

    // EdgeConv: ec(0)+g2ec(1), ec(1)+g2ec(2), ec(2)+out
    for (int L = 1; L < 3; L++) {
        k_ec_g2<1, 0><<<GRID, 256>>>(dstoff, gnbr, A[cur], B[cur],
                                     ecw + L * 128 * H, ecb + L * H, A[1 - cur], B[1 - cur]);
        cur ^= 1;
    }
    k_ec_out<<<GRID, 256>>>(dstoff, gnbr, A[cur], B[cur], ow, ob, (float*)d_out);
}

// round 5
// speedup vs baseline: 2.0777x; 2.0777x over previous
#include <cuda_runtime.h>

// Problem constants (fixed by the dataset)
constexpr int NN  = 50000;   // nodes
constexpr int EE  = 800000;  // edges
constexpr int PER = 200000;  // edges per emulsion order (EE/4)
constexpr int H   = 64;      // hidden dim

typedef unsigned long long u64;

// ---------------- scratch (static device globals; no allocation) ----------
__device__ float g_x[NN * H];        // node features
__device__ float g_A[NN * H];        // dst-side pre-GEMM
__device__ float g_B[NN * H];        // src-side pre-GEMM
__device__ int   g_deg[5 * NN];      // degrees: 4 src-slices + 1 dst
__device__ int   g_off[5 * (NN + 1)];
__device__ int   g_cur[5 * (NN + 1)];
__device__ int2  g_edg[EE];          // src-CSR: (dst, ef bits)
__device__ int   g_nbr[EE];          // dst-CSR: src

// ---------------- packed f32x2 helpers -------------------------------------
__device__ __forceinline__ u64 pk(float lo, float hi) {
    u64 r; asm("mov.b64 %0, {%1, %2};" : "=l"(r) : "f"(lo), "f"(hi)); return r;
}
__device__ __forceinline__ float2 unpk(u64 v) {
    float2 f; asm("mov.b64 {%0, %1}, %2;" : "=f"(f.x), "=f"(f.y) : "l"(v)); return f;
}
__device__ __forceinline__ void ffma2(u64& d, u64 a, u64 b) {
    asm("fma.rn.f32x2 %0, %1, %2, %0;" : "+l"(d) : "l"(a), "l"(b));
}

// ---------------- CSR build ------------------------------------------------
__global__ void k_zero(int* p, int n) {
    int i = blockIdx.x * blockDim.x + threadIdx.x;
    if (i < n) p[i] = 0;
}

__global__ void k_hist(const int* __restrict__ ei) {
    int e = blockIdx.x * blockDim.x + threadIdx.x;
    if (e >= EE) return;
    int s = ei[e], d = ei[EE + e];
    int sl = e / PER;
    atomicAdd(&g_deg[sl * NN + s], 1);
    atomicAdd(&g_deg[4 * NN + d], 1);
}

// grid = 5 blocks (one per array), block = 1024
__global__ void k_scan() {
    int a = blockIdx.x;
    const int* deg = g_deg + a * NN;
    int* off = g_off + a * (NN + 1);
    int* cur = g_cur + a * (NN + 1);
    int t = threadIdx.x;
    const int CH = (NN + 1023) / 1024;  // 49
    int begin = t * CH;
    int end = begin + CH; if (end > NN) end = NN; if (begin > NN) begin = NN;
    int s = 0;
    for (int i = begin; i < end; i++) s += deg[i];
    __shared__ int sh[1024];
    sh[t] = s;
    __syncthreads();
    for (int d = 1; d < 1024; d <<= 1) {
        int v = 0;
        if (t >= d) v = sh[t - d];
        __syncthreads();
        if (t >= d) sh[t] += v;
        __syncthreads();
    }
    int pre = (t == 0) ? 0 : sh[t - 1];
    for (int i = begin; i < end; i++) {
        off[i] = pre; cur[i] = pre;
        pre += deg[i];
    }
    if (t == 1023) off[NN] = sh[1023];
}

__global__ void k_scatter(const int* __restrict__ ei, const float* __restrict__ ef) {
    int e = blockIdx.x * blockDim.x + threadIdx.x;
    if (e >= EE) return;
    int s = ei[e], d = ei[EE + e];
    int sl = e / PER;
    int p = atomicAdd(&g_cur[sl * (NN + 1) + s], 1);
    g_edg[sl * PER + p] = make_int2(d, __float_as_int(ef[e]));
    int q = atomicAdd(&g_cur[4 * (NN + 1) + d], 1);
    g_nbr[q] = s;
}

// ---------------- lin0 GEMM (K=10, small): out = relu(x@W+b) ---------------
__global__ void k_gemm1_k10(const float* __restrict__ xin, const float* __restrict__ W,
                            const float* __restrict__ bias, float* __restrict__ out,
                            int rowsPerBlock) {
    const int K = 10;
    int t = threadIdx.x;  // column
    float w[K];
#pragma unroll
    for (int k = 0; k < K; k++) w[k] = W[k * H + t];
    float bv = bias[t];
    __shared__ float xs[4][K];
    int row0 = blockIdx.x * rowsPerBlock;
    int row1 = row0 + rowsPerBlock; if (row1 > NN) row1 = NN;
    for (int r = row0; r < row1; r += 4) {
        for (int i = t; i < 4 * K; i += 64) xs[i / K][i % K] = xin[r * K + i];
        __syncthreads();
        float a0 = bv, a1 = bv, a2 = bv, a3 = bv;
#pragma unroll
        for (int k = 0; k < K; k++) {
            float wv = w[k];
            a0 = fmaf(xs[0][k], wv, a0);
            a1 = fmaf(xs[1][k], wv, a1);
            a2 = fmaf(xs[2][k], wv, a2);
            a3 = fmaf(xs[3][k], wv, a3);
        }
        out[(r + 0) * H + t] = fmaxf(a0, 0.f);
        out[(r + 1) * H + t] = fmaxf(a1, 0.f);
        out[(r + 2) * H + t] = fmaxf(a2, 0.f);
        out[(r + 3) * H + t] = fmaxf(a3, 0.f);
        __syncthreads();
    }
}

// ---------------- lin GEMM (K=64), packed f32x2, 2 cols/thread, 1 warp -----
__global__ void __launch_bounds__(32) k_gemm1p(
        const float* __restrict__ xin, const float* __restrict__ W,
        const float* __restrict__ bias, float* __restrict__ out, int rowsPerBlock) {
    int t = threadIdx.x;
    int c0 = t, c1 = t + 32;
    u64 w0[32], w1[32];
#pragma unroll
    for (int k = 0; k < 32; k++) {
        w0[k] = pk(W[(2 * k) * H + c0], W[(2 * k + 1) * H + c0]);
        w1[k] = pk(W[(2 * k) * H + c1], W[(2 * k + 1) * H + c1]);
    }
    float b0 = bias[c0], b1 = bias[c1];
    __shared__ __align__(16) u64 xs[4][32];
    int row0 = blockIdx.x * rowsPerBlock;
    int row1 = row0 + rowsPerBlock; if (row1 > NN) row1 = NN;
    for (int r = row0; r < row1; r += 4) {
        const float4* src = (const float4*)(xin + r * H);
        ((float4*)xs)[t] = src[t];
        ((float4*)xs)[t + 32] = src[t + 32];
        __syncthreads();
        u64 a0 = 0, a1 = 0, a2 = 0, a3 = 0, e0 = 0, e1 = 0, e2 = 0, e3 = 0;
#pragma unroll
        for (int k2 = 0; k2 < 16; k2++) {
            ulonglong2 x0 = ((const ulonglong2*)xs[0])[k2];
            ulonglong2 x1 = ((const ulonglong2*)xs[1])[k2];
            ulonglong2 x2 = ((const ulonglong2*)xs[2])[k2];
            ulonglong2 x3 = ((const ulonglong2*)xs[3])[k2];
            u64 wa = w0[2 * k2], wb = w0[2 * k2 + 1];
            u64 wc = w1[2 * k2], wd = w1[2 * k2 + 1];
            ffma2(a0, x0.x, wa); ffma2(a0, x0.y, wb);
            ffma2(e0, x0.x, wc); ffma2(e0, x0.y, wd);
            ffma2(a1, x1.x, wa); ffma2(a1, x1.y, wb);
            ffma2(e1, x1.x, wc); ffma2(e1, x1.y, wd);
            ffma2(a2, x2.x, wa); ffma2(a2, x2.y, wb);
            ffma2(e2, x2.x, wc); ffma2(e2, x2.y, wd);
            ffma2(a3, x3.x, wa); ffma2(a3, x3.y, wb);
            ffma2(e3, x3.x, wc); ffma2(e3, x3.y, wd);
        }
        float2 f;
        f = unpk(a0); out[(r + 0) * H + c0] = fmaxf(f.x + f.y + b0, 0.f);
        f = unpk(a1); out[(r + 1) * H + c0] = fmaxf(f.x + f.y + b0, 0.f);
        f = unpk(a2); out[(r + 2) * H + c0] = fmaxf(f.x + f.y + b0, 0.f);
        f = unpk(a3); out[(r + 3) * H + c0] = fmaxf(f.x + f.y + b0, 0.f);
        f = unpk(e0); out[(r + 0) * H + c1] = fmaxf(f.x + f.y + b1, 0.f);
        f = unpk(e1); out[(r + 1) * H + c1] = fmaxf(f.x + f.y + b1, 0.f);
        f = unpk(e2); out[(r + 2) * H + c1] = fmaxf(f.x + f.y + b1, 0.f);
        f = unpk(e3); out[(r + 3) * H + c1] = fmaxf(f.x + f.y + b1, 0.f);
        __syncthreads();
    }
}

// ---------------- fused dual GEMM, packed f32x2, A/B split over 128 thr ----
// A = x@(W[0:64]-W[64:128]) (+bias?),  B = x@W[64:128] (+bias?).
// Thread t<64 computes A column t; thread t>=64 computes B column t-64.
template <int BIAS_A, int BIAS_B>
__global__ void __launch_bounds__(128) k_gemm2(
        const float* __restrict__ xin, const float* __restrict__ W,
        const float* __restrict__ bias, float* __restrict__ outA,
        float* __restrict__ outB, int rowsPerBlock) {
    int t = threadIdx.x;
    int c = t & 63;
    bool isB = t >= 64;
    u64 w[32];
    if (isB) {
#pragma unroll
        for (int k = 0; k < 32; k++)
            w[k] = pk(W[(H + 2 * k) * H + c], W[(H + 2 * k + 1) * H + c]);
    } else {
#pragma unroll
        for (int k = 0; k < 32; k++)
            w[k] = pk(W[(2 * k) * H + c] - W[(H + 2 * k) * H + c],
                      W[(2 * k + 1) * H + c] - W[(H + 2 * k + 1) * H + c]);
    }
    float bv = (isB ? BIAS_B : BIAS_A) ? bias[c] : 0.f;
    float* o = isB ? outB : outA;
    __shared__ __align__(16) u64 xs[4][32];
    int row0 = blockIdx.x * rowsPerBlock;
    int row1 = row0 + rowsPerBlock; if (row1 > NN) row1 = NN;
    for (int r = row0; r < row1; r += 4) {
        const float4* src = (const float4*)(xin + r * H);
        if (t < 64) ((float4*)xs)[t] = src[t];  // 64 float4 = 4 rows x 64 floats
        __syncthreads();
        u64 a0 = 0, a1 = 0, a2 = 0, a3 = 0;
#pragma unroll
        for (int k2 = 0; k2 < 16; k2++) {
            ulonglong2 x0 = ((const ulonglong2*)xs[0])[k2];
            ulonglong2 x1 = ((const ulonglong2*)xs[1])[k2];
            ulonglong2 x2 = ((const ulonglong2*)xs[2])[k2];
            ulonglong2 x3 = ((const ulonglong2*)xs[3])[k2];
            u64 w0 = w[2 * k2], w1 = w[2 * k2 + 1];
            ffma2(a0, x0.x, w0); ffma2(a0, x0.y, w1);
            ffma2(a1, x1.x, w0); ffma2(a1, x1.y, w1);
            ffma2(a2, x2.x, w0); ffma2(a2, x2.y, w1);
            ffma2(a3, x3.x, w0); ffma2(a3, x3.y, w1);
        }
        float2 f;
        f = unpk(a0); o[(r + 0) * H + c] = f.x + f.y + bv;
        f = unpk(a1); o[(r + 1) * H + c] = f.x + f.y + bv;
        f = unpk(a2); o[(r + 2) * H + c] = f.x + f.y + bv;
        f = unpk(a3); o[(r + 3) * H + c] = f.x + f.y + bv;
        __syncthreads();
    }
}

// ---------------- EmulsionConv edge pass (one order slice) -----------------
// 64-lane group per node n (aggregating at src):
//   x[n] = (x[n] + sum_e relu(A[dst_e] + B[n] + ef_e*w2)) / 2
__global__ void k_em_edge(const int* __restrict__ off, const int2* __restrict__ edg,
                          const float* __restrict__ w2) {
    int n = (blockIdx.x * blockDim.x + threadIdx.x) >> 6;
    int lane = threadIdx.x & 63;
    if (n >= NN) return;
    int e0 = off[n], e1 = off[n + 1];
    float yb = g_B[n * H + lane];
    float w2v = w2[lane];
    float a = 0.f;
    for (int e = e0; e < e1; e++) {
        int2 p = edg[e];
        a += fmaxf(g_A[p.x * H + lane] + fmaf(__int_as_float(p.y), w2v, yb), 0.f);
    }
    g_x[n * H + lane] = (g_x[n * H + lane] + a) * 0.5f;
}

// ---------------- EdgeConv edge pass ---------------------------------------
// 64-lane group per node n (aggregating at dst): x[n] = max(0, max_e (A[n]+B[src_e]))
__global__ void k_ec_edge(const int* __restrict__ off, const int* __restrict__ nbr) {
    int n = (blockIdx.x * blockDim.x + threadIdx.x) >> 6;
    int lane = threadIdx.x & 63;
    if (n >= NN) return;
    int e0 = off[n], e1 = off[n + 1];
    float za = g_A[n * H + lane];
    float a = 0.f;  // relu floor: max over messages of relu == max(0, max msg)
    for (int e = e0; e < e1; e++) {
        int s = nbr[e];
        a = fmaxf(a, za + g_B[s * H + lane]);
    }
    g_x[n * H + lane] = a;
}

// ---------------- output head: out[N,10] = x@ow[64,10] + ob -----------------
__global__ void k_out(const float* __restrict__ ow, const float* __restrict__ ob,
                      float* __restrict__ out) {
    __shared__ float w[64 * 10];
    __shared__ float b[10];
    int t = threadIdx.x;
    for (int i = t; i < 640; i += blockDim.x) w[i] = ow[i];
    if (t < 10) b[t] = ob[t];
    __syncthreads();
    int idx = blockIdx.x * blockDim.x + t;
    if (idx >= NN * 10) return;
    int n = idx / 10, c = idx % 10;
    float acc = b[c];
#pragma unroll
    for (int k = 0; k < 64; k++) acc = fmaf(g_x[n * H + k], w[k * 10 + c], acc);
    out[idx] = acc;
}

// ---------------- orchestration --------------------------------------------
extern "C" void kernel_launch(void* const* d_in, const int* in_sizes, int n_in,
                              void* d_out, int out_size) {
    const float* x0  = (const float*)d_in[0];
    const int*   ei  = (const int*)d_in[1];
    const float* ef  = (const float*)d_in[2];
    const float* lw[3] = {(const float*)d_in[3], (const float*)d_in[5], (const float*)d_in[7]};
    const float* lb[3] = {(const float*)d_in[4], (const float*)d_in[6], (const float*)d_in[8]};
    const float* emw = (const float*)d_in[9];   // [3,129,64]
    const float* emb = (const float*)d_in[10];  // [3,64]
    const float* ecw = (const float*)d_in[11];  // [3,128,64]
    const float* ecb = (const float*)d_in[12];  // [3,64]
    const float* ow  = (const float*)d_in[13];
    const float* ob  = (const float*)d_in[14];

    float *gx, *gA, *gB;
    int *gdeg, *goff, *gnbr;
    int2* gedg;
    cudaGetSymbolAddress((void**)&gx,   g_x);
    cudaGetSymbolAddress((void**)&gA,   g_A);
    cudaGetSymbolAddress((void**)&gB,   g_B);
    cudaGetSymbolAddress((void**)&gdeg, g_deg);
    cudaGetSymbolAddress((void**)&goff, g_off);
    cudaGetSymbolAddress((void**)&gnbr, g_nbr);
    cudaGetSymbolAddress((void**)&gedg, g_edg);

    // CSR build (per launch, deterministic workload)
    k_zero<<<(5 * NN + 255) / 256, 256>>>(gdeg, 5 * NN);
    k_hist<<<(EE + 255) / 256, 256>>>(ei);
    k_scan<<<5, 1024>>>();
    k_scatter<<<(EE + 255) / 256, 256>>>(ei, ef);

    const int RPB0 = 52;                          // lin0 (K=10)
    const int G0 = (NN + RPB0 - 1) / RPB0;
    const int RPB1 = 28;                          // lin packed (1 warp/block)
    const int G1 = (NN + RPB1 - 1) / RPB1;
    const int RPB2 = 68;                          // dual GEMM (128 thr/block)
    const int G2 = (NN + RPB2 - 1) / RPB2;
    const int GE = (NN * 64 + 255) / 256;         // 64-lane group per node

    // lin0 (K=10) + 3x (lin, EmulsionConv x4 orders)
    k_gemm1_k10<<<G0, 64>>>(x0, lw[0], lb[0], gx, RPB0);
    for (int L = 0; L < 3; L++) {
        if (L > 0) k_gemm1p<<<G1, 32>>>(gx, lw[L], lb[L], gx, RPB1);
        const float* W = emw + L * 129 * H;
        const float* b = emb + L * H;
        for (int o = 0; o < 4; o++) {
            k_gemm2<0, 1><<<G2, 128>>>(gx, W, b, gA, gB, RPB2);  // bias folded into B (src side)
            k_em_edge<<<GE, 256>>>(goff + o * (NN + 1), gedg + o * PER, W + 128 * H);
        }
    }

    // 3x EdgeConv
    for (int L = 0; L < 3; L++) {
        k_gemm2<1, 0><<<G2, 128>>>(gx, ecw + L * 128 * H, ecb + L * H, gA, gB, RPB2);  // bias in A (dst side)
        k_ec_edge<<<GE, 256>>>(goff + 4 * (NN + 1), gnbr);
    }

    // output head
    k_out<<<(NN * 10 + 255) / 256, 256>>>(ow, ob, (float*)d_out);
}